// round 7
// baseline (speedup 1.0000x reference)
#include <cuda_runtime.h>

// Problem constants
#define NN 13          // nodes
#define DD 16          // feature dim
#define NB 8           // batch elements per block
#define TPB 128        // threads per block
#define TB 16          // threads per batch element (1 col each)

// Per-batch shared region, stride RS floats (RS % 32 == 8).
//  [0..832)    adj padded: 4 ch x 13 rows x stride16
//              (decoder reuse: temp kk0 [0..208), temp kk1 [208..416), recon [416..754))
//  [832..1040)  X0 buffer (13 x 16)
//  [1040..1248) X1 buffer (13 x 16)
#define RS   1256
#define X0OFF 832
#define X1OFF 1040

// Block-common weights region (verbatim copies of input layout)
#define WB     (8*RS)          // 10048
#define OW     (WB)            // init_weight [13][16]            208
#define OW0    (WB+208)        // mlp_w0 [l][c][dp]              1024
#define OW1    (WB+1232)       // mlp_w1                         1024
#define OB0    (WB+2256)       // mlp_b0 [l][16]                   64
#define OB1    (WB+2320)       //                                  64
#define OF1    (WB+2384)       // fc1_w [c][dp]                   256
#define OF2    (WB+2640)       //                                 256
#define OF1B   (WB+2896)       //                                  16
#define OF2B   (WB+2912)       //                                  16
#define ODEC   (WB+2928)       // dec_w [k][d][l]                1024
#define ODECB  (WB+3952)       //                                  64
#define OBIS   (WB+4016)       // bn_in scale  [l][13]             52
#define OBIB   (WB+4068)       // bn_in bias                       52
#define OBOS   (WB+4120)       // bn_out scale                     52
#define OBOB   (WB+4172)       // bn_out bias                      52
#define OEPS   (WB+4224)       // 1+eps [4]                         4
#define SH_FLOATS (WB+4228)    // 14276
#define SMEM_BYTES (SH_FLOATS*4)

// Output layout: recon (B,4,13,13) | mu (B,13,16) | logvar (B,13,16)
#define RECON_ELEMS (676ull)
#define MU_OFF  (32768ull*676ull)
#define LV_OFF  (MU_OFF + 32768ull*208ull)

// Triangular pair decode tables for p in [0,91): (n<=m)
__constant__ unsigned char PN[91] = {
 0,0,0,0,0,0,0,0,0,0,0,0,0,
 1,1,1,1,1,1,1,1,1,1,1,1,
 2,2,2,2,2,2,2,2,2,2,2,
 3,3,3,3,3,3,3,3,3,3,
 4,4,4,4,4,4,4,4,4,
 5,5,5,5,5,5,5,5,
 6,6,6,6,6,6,6,
 7,7,7,7,7,7,
 8,8,8,8,8,
 9,9,9,9,
 10,10,10,
 11,11,
 12};
__constant__ unsigned char PM[91] = {
 0,1,2,3,4,5,6,7,8,9,10,11,12,
 1,2,3,4,5,6,7,8,9,10,11,12,
 2,3,4,5,6,7,8,9,10,11,12,
 3,4,5,6,7,8,9,10,11,12,
 4,5,6,7,8,9,10,11,12,
 5,6,7,8,9,10,11,12,
 6,7,8,9,10,11,12,
 7,8,9,10,11,12,
 8,9,10,11,12,
 9,10,11,12,
 10,11,12,
 11,12,
 12};

struct W16 { float4 a, b, c, d; };

__device__ __forceinline__ W16 ldw16(const float* __restrict__ p) {
    W16 w;
    w.a = *reinterpret_cast<const float4*>(p);
    w.b = *reinterpret_cast<const float4*>(p + 4);
    w.c = *reinterpret_cast<const float4*>(p + 8);
    w.d = *reinterpret_cast<const float4*>(p + 12);
    return w;
}

__device__ __forceinline__ float dot16(const float4& xA, const float4& xB,
                                       const float4& xC, const float4& xD,
                                       const W16& w, float acc) {
    acc = fmaf(xA.x, w.a.x, acc); acc = fmaf(xA.y, w.a.y, acc);
    acc = fmaf(xA.z, w.a.z, acc); acc = fmaf(xA.w, w.a.w, acc);
    acc = fmaf(xB.x, w.b.x, acc); acc = fmaf(xB.y, w.b.y, acc);
    acc = fmaf(xB.z, w.b.z, acc); acc = fmaf(xB.w, w.b.w, acc);
    acc = fmaf(xC.x, w.c.x, acc); acc = fmaf(xC.y, w.c.y, acc);
    acc = fmaf(xC.z, w.c.z, acc); acc = fmaf(xC.w, w.c.w, acc);
    acc = fmaf(xD.x, w.d.x, acc); acc = fmaf(xD.y, w.d.y, acc);
    acc = fmaf(xD.z, w.d.z, acc); acc = fmaf(xD.w, w.d.w, acc);
    return acc;
}

__global__ void __launch_bounds__(TPB, 3) vae_kernel(
    const float* __restrict__ adj,
    const float* __restrict__ initW,
    const float* __restrict__ eps_param,
    const float* __restrict__ mlp_w0,
    const float* __restrict__ mlp_b0,
    const float* __restrict__ mlp_w1,
    const float* __restrict__ mlp_b1,
    const float* __restrict__ bn_in_gamma,
    const float* __restrict__ bn_in_beta,
    const float* __restrict__ bn_in_mean,
    const float* __restrict__ bn_in_var,
    const float* __restrict__ bn_out_gamma,
    const float* __restrict__ bn_out_beta,
    const float* __restrict__ bn_out_mean,
    const float* __restrict__ bn_out_var,
    const float* __restrict__ fc1_w,
    const float* __restrict__ fc1_b,
    const float* __restrict__ fc2_w,
    const float* __restrict__ fc2_b,
    const float* __restrict__ dec_w,
    const float* __restrict__ dec_b,
    float* __restrict__ out)
{
    extern __shared__ float sh[];
    const int tid = threadIdx.x;

    // ---------------- Phase A: cooperative loads ----------------
    {
        const float4* src = reinterpret_cast<const float4*>(adj + (size_t)blockIdx.x * NB * 676);
        for (int c = tid; c < NB * 169; c += TPB) {
            int bl = c / 169;
            int r  = c - bl * 169;
            float4 v = src[c];
            float vv[4] = {v.x, v.y, v.z, v.w};
            int e = 4 * r;
            #pragma unroll
            for (int j = 0; j < 4; ++j) {
                int ee = e + j;
                int ch = ee / 169;
                int p  = ee - ch * 169;
                int n  = p / 13;
                int m  = p - n * 13;
                sh[bl * RS + ch * 208 + n * 16 + m] = vv[j];
            }
        }
    }
    for (int j = tid; j < 208; j += TPB) sh[OW + j] = initW[j];
    for (int j = tid; j < 1024; j += TPB) {
        sh[OW0 + j]  = mlp_w0[j];
        sh[OW1 + j]  = mlp_w1[j];
        sh[ODEC + j] = dec_w[j];
    }
    for (int j = tid; j < 64; j += TPB) {
        sh[OB0 + j] = mlp_b0[j];
        sh[OB1 + j] = mlp_b1[j];
        sh[ODECB + j] = dec_b[j];
    }
    for (int j = tid; j < 256; j += TPB) {
        sh[OF1 + j] = fc1_w[j];
        sh[OF2 + j] = fc2_w[j];
    }
    for (int j = tid; j < 16; j += TPB) {
        sh[OF1B + j] = fc1_b[j];
        sh[OF2B + j] = fc2_b[j];
    }
    for (int j = tid; j < 52; j += TPB) {
        float s = bn_in_gamma[j] * rsqrtf(bn_in_var[j] + 1e-5f);
        sh[OBIS + j] = s;
        sh[OBIB + j] = bn_in_beta[j] - bn_in_mean[j] * s;
        float so = bn_out_gamma[j] * rsqrtf(bn_out_var[j] + 1e-5f);
        sh[OBOS + j] = so;
        sh[OBOB + j] = bn_out_beta[j] - bn_out_mean[j] * so;
    }
    for (int j = tid; j < 4; j += TPB) sh[OEPS + j] = 1.0f + eps_param[j];
    __syncthreads();

    // ---------------- Phase B: per-batch work (warp-local) ----------------
    const int lane = tid & 31;
    const int warp = tid >> 5;
    const int grp  = lane >> 4;       // batch within warp (0..1)
    const int t    = lane & 15;       // thread owns column c = t
    const int bl   = warp * 2 + grp;
    const size_t b = (size_t)blockIdx.x * NB + bl;
    float* R  = sh + bl * RS;
    float* X0 = R + X0OFF;
    float* X1 = R + X1OFF;
    const int iCh = t >> 2;           // adj channel for owned column (G=4)

    // S[n][*] = sum_i adj[i][n][*]  (padded stride 16, into X1)
    for (int idx = t; idx < 52; idx += TB) {
        int n = idx >> 2, q = idx & 3;
        const float* p0 = R + n * 16 + q * 4;
        float4 a  = *reinterpret_cast<const float4*>(p0);
        float4 c1 = *reinterpret_cast<const float4*>(p0 + 208);
        float4 c2 = *reinterpret_cast<const float4*>(p0 + 416);
        float4 c3 = *reinterpret_cast<const float4*>(p0 + 624);
        float4 s;
        s.x = a.x + c1.x + c2.x + c3.x;
        s.y = a.y + c1.y + c2.y + c3.y;
        s.z = a.z + c1.z + c2.z + c3.z;
        s.w = a.w + c1.w + c2.w + c3.w;
        *reinterpret_cast<float4*>(X1 + n * 16 + q * 4) = s;
    }
    __syncwarp();

    float x[NN];
    // x[n] = sum_m S[n][m] * W[m][t]   (W column t -> regs, stride-16 conflict-free)
    {
        float wi[NN];
        #pragma unroll
        for (int m = 0; m < NN; ++m) wi[m] = sh[OW + m * 16 + t];
        #pragma unroll
        for (int n = 0; n < NN; ++n) {
            const float* Sr = X1 + n * 16;
            float4 sA = *reinterpret_cast<const float4*>(Sr);
            float4 sB = *reinterpret_cast<const float4*>(Sr + 4);
            float4 sC = *reinterpret_cast<const float4*>(Sr + 8);
            float s12 = Sr[12];
            float a0 = sA.x*wi[0] + sA.y*wi[1] + sA.z*wi[2] + sA.w*wi[3]
                     + sB.x*wi[4] + sB.y*wi[5] + sB.z*wi[6] + sB.w*wi[7]
                     + sC.x*wi[8] + sC.y*wi[9] + sC.z*wi[10] + sC.w*wi[11]
                     + s12 * wi[12];
            x[n] = a0;
        }
    }

    // 4 GIN layers
    #pragma unroll 1
    for (int l = 0; l < 4; ++l) {
        float ep = sh[OEPS + l];
        const float* A = R + iCh * 208;

        // agg: X0[n][t] = ep*x[n] + (A @ x)[n]
        #pragma unroll
        for (int n = 0; n < NN; ++n) {
            const float* Ar = A + n * 16;
            float4 aA = *reinterpret_cast<const float4*>(Ar);
            float4 aB = *reinterpret_cast<const float4*>(Ar + 4);
            float4 aC = *reinterpret_cast<const float4*>(Ar + 8);
            float a12 = Ar[12];
            float s0 = aA.x*x[0] + aA.y*x[1] + aA.z*x[2] + aA.w*x[3]
                     + aB.x*x[4] + aB.y*x[5] + aB.z*x[6] + aB.w*x[7]
                     + aC.x*x[8] + aC.y*x[9] + aC.z*x[10] + aC.w*x[11]
                     + a12 * x[12];
            X0[n * 16 + t] = fmaf(ep, x[n], s0);
        }
        __syncwarp();

        // MLP1 + bn_in + leaky: X0 -> X1
        {
            W16 w = ldw16(sh + OW0 + (l << 8) + t * 16);
            float bb = sh[OB0 + (l << 4) + t];
            #pragma unroll
            for (int n = 0; n < NN; ++n) {
                const float* Xr = X0 + n * 16;
                float4 xA = *reinterpret_cast<const float4*>(Xr);
                float4 xB = *reinterpret_cast<const float4*>(Xr + 4);
                float4 xC = *reinterpret_cast<const float4*>(Xr + 8);
                float4 xD = *reinterpret_cast<const float4*>(Xr + 12);
                float a0 = dot16(xA, xB, xC, xD, w, bb);
                float sc = sh[OBIS + l * 13 + n], bi = sh[OBIB + l * 13 + n];
                a0 = fmaf(a0, sc, bi);
                a0 = (a0 >= 0.f) ? a0 : 0.01f * a0;
                X1[n * 16 + t] = a0;
            }
        }
        __syncwarp();

        // MLP2 + bn_out + leaky: X1 -> x regs
        {
            W16 w = ldw16(sh + OW1 + (l << 8) + t * 16);
            float bb = sh[OB1 + (l << 4) + t];
            #pragma unroll
            for (int n = 0; n < NN; ++n) {
                const float* Xr = X1 + n * 16;
                float4 xA = *reinterpret_cast<const float4*>(Xr);
                float4 xB = *reinterpret_cast<const float4*>(Xr + 4);
                float4 xC = *reinterpret_cast<const float4*>(Xr + 8);
                float4 xD = *reinterpret_cast<const float4*>(Xr + 12);
                float a0 = dot16(xA, xB, xC, xD, w, bb);
                float sc = sh[OBOS + l * 13 + n], bi = sh[OBOB + l * 13 + n];
                a0 = fmaf(a0, sc, bi);
                x[n] = (a0 >= 0.f) ? a0 : 0.01f * a0;
            }
        }
        __syncwarp();
    }

    // Publish final x to X0 for the fc layers
    #pragma unroll
    for (int n = 0; n < NN; ++n) X0[n * 16 + t] = x[n];
    __syncwarp();

    float mu[NN];
    // fc1 -> mu (regs + gmem)
    {
        W16 w = ldw16(&sh[OF1 + t * 16]);
        float fb = sh[OF1B + t];
        float* muG = out + MU_OFF + b * 208;
        #pragma unroll
        for (int n = 0; n < NN; ++n) {
            const float* Xr = X0 + n * 16;
            float4 xA = *reinterpret_cast<const float4*>(Xr);
            float4 xB = *reinterpret_cast<const float4*>(Xr + 4);
            float4 xC = *reinterpret_cast<const float4*>(Xr + 8);
            float4 xD = *reinterpret_cast<const float4*>(Xr + 12);
            float a0 = dot16(xA, xB, xC, xD, w, fb);
            mu[n] = a0;
            muG[n * 16 + t] = a0;
        }
    }
    // fc2 -> logvar (gmem only)
    {
        W16 w = ldw16(&sh[OF2 + t * 16]);
        float fb = sh[OF2B + t];
        float* lvG = out + LV_OFF + b * 208;
        #pragma unroll
        for (int n = 0; n < NN; ++n) {
            const float* Xr = X0 + n * 16;
            float4 xA = *reinterpret_cast<const float4*>(Xr);
            float4 xB = *reinterpret_cast<const float4*>(Xr + 4);
            float4 xC = *reinterpret_cast<const float4*>(Xr + 8);
            float4 xD = *reinterpret_cast<const float4*>(Xr + 12);
            lvG[n * 16 + t] = dot16(xA, xB, xC, xD, w, fb);
        }
    }
    __syncwarp();
    // Publish mu to X1 for the decoder
    #pragma unroll
    for (int n = 0; n < NN; ++n) X1[n * 16 + t] = mu[n];
    __syncwarp();

    // Decoder in two k-chunks; temp at R[0..416), recon scratch at R[416..754)
    float* outR = out + b * RECON_ELEMS;
    float* Rc = R + 416;
    #pragma unroll 1
    for (int c = 0; c < 2; ++c) {
        #pragma unroll
        for (int kk = 0; kk < 2; ++kk) {
            int k = 2 * c + kk;
            W16 w = ldw16(sh + ODEC + (k << 8) + t * 16);
            float db = sh[ODECB + (k << 4) + t];
            #pragma unroll
            for (int n = 0; n < NN; ++n) {
                const float* Zr = X1 + n * 16;
                float4 zA = *reinterpret_cast<const float4*>(Zr);
                float4 zB = *reinterpret_cast<const float4*>(Zr + 4);
                float4 zC = *reinterpret_cast<const float4*>(Zr + 8);
                float4 zD = *reinterpret_cast<const float4*>(Zr + 12);
                R[kk * 208 + n * 16 + t] = dot16(zA, zB, zC, zD, w, db);
            }
        }
        __syncwarp();
        // recon = relu(temp @ temp^T), symmetric half
        for (int idx = t; idx < 182; idx += TB) {
            int kk = (idx >= 91) ? 1 : 0;
            int p = idx - kk * 91;
            int n = PN[p], m = PM[p];
            const float4* tn = reinterpret_cast<const float4*>(&R[kk * 208 + n * 16]);
            const float4* tm = reinterpret_cast<const float4*>(&R[kk * 208 + m * 16]);
            float s = 0.f;
            #pragma unroll
            for (int q = 0; q < 4; ++q) {
                float4 a = tn[q], bq = tm[q];
                s += a.x * bq.x + a.y * bq.y + a.z * bq.z + a.w * bq.w;
            }
            s = fmaxf(s, 0.f);
            Rc[kk * 169 + n * 13 + m] = s;
            Rc[kk * 169 + m * 13 + n] = s;
        }
        __syncwarp();
        // coalesced write: 338 floats = 169 float2
        {
            const float2* src2 = reinterpret_cast<const float2*>(Rc);
            float2* dst2 = reinterpret_cast<float2*>(outR + c * 338);
            for (int j = t; j < 169; j += TB) dst2[j] = src2[j];
        }
        __syncwarp();
    }
}

extern "C" void kernel_launch(void* const* d_in, const int* in_sizes, int n_in,
                              void* d_out, int out_size) {
    (void)in_sizes; (void)n_in; (void)out_size;
    cudaFuncSetAttribute(vae_kernel, cudaFuncAttributeMaxDynamicSharedMemorySize, SMEM_BYTES);
    vae_kernel<<<32768 / NB, TPB, SMEM_BYTES>>>(
        (const float*)d_in[0],  (const float*)d_in[1],  (const float*)d_in[2],
        (const float*)d_in[3],  (const float*)d_in[4],  (const float*)d_in[5],
        (const float*)d_in[6],  (const float*)d_in[7],  (const float*)d_in[8],
        (const float*)d_in[9],  (const float*)d_in[10], (const float*)d_in[11],
        (const float*)d_in[12], (const float*)d_in[13], (const float*)d_in[14],
        (const float*)d_in[15], (const float*)d_in[16], (const float*)d_in[17],
        (const float*)d_in[18], (const float*)d_in[19], (const float*)d_in[20],
        (float*)d_out);
}

// round 9
// speedup vs baseline: 1.1744x; 1.1744x over previous
#include <cuda_runtime.h>

// Problem constants
#define NN 13          // nodes
#define DD 16          // feature dim
#define NB 16          // batch elements per block
#define TPB 128        // threads per block
#define TB 8           // threads per batch element (2 cols each)

// Per-batch shared region, stride RS floats (RS % 32 == 8 -> 4 warp-groups staggered).
//  [0..832)     adj padded: 4 ch x 13 rows x stride16
//               (decoder reuse: temp kk0 [0..208), kk1 [208..416), recon [416..754))
//  [832..1040)  X0 buffer (13 x 16)
//  [1040..1248) X1 buffer (13 x 16)
#define RS    1256
#define X0OFF 832
#define X1OFF 1040

// Block-common weights region
#define WB     (16*RS)         // 20096
#define OW     (WB)            // init_weight [m][c] natural        208
#define OW0    (WB+208)        // mlp_w0 transposed [l][dp][c]     1024
#define OW1    (WB+1232)       // mlp_w1 transposed                1024
#define OB0    (WB+2256)       // mlp_b0 [l][16]                     64
#define OB1    (WB+2320)       //                                    64
#define OF1    (WB+2384)       // fc1_w transposed [dp][c]          256
#define OF2    (WB+2640)       //                                   256
#define OF1B   (WB+2896)       //                                    16
#define OF2B   (WB+2912)       //                                    16
#define ODEC   (WB+2928)       // dec_w transposed [k][l][d]       1024
#define ODECB  (WB+3952)       //                                    64
#define OBNI   (WB+4016)       // bn_in  {scale,bias} [l][n][2]     104
#define OBNO   (WB+4120)       // bn_out {scale,bias}               104
#define OEPS   (WB+4224)       // 1+eps [4]                           4
#define SH_FLOATS (WB+4228)    // 24324
#define SMEM_BYTES (SH_FLOATS*4)

// Output layout: recon (B,4,13,13) | mu (B,13,16) | logvar (B,13,16)
#define RECON_ELEMS (676ull)
#define MU_OFF  (32768ull*676ull)
#define LV_OFF  (MU_OFF + 32768ull*208ull)

// Triangular pair decode tables for p in [0,91): (n<=m)
__constant__ unsigned char PN[91] = {
 0,0,0,0,0,0,0,0,0,0,0,0,0,
 1,1,1,1,1,1,1,1,1,1,1,1,
 2,2,2,2,2,2,2,2,2,2,2,
 3,3,3,3,3,3,3,3,3,3,
 4,4,4,4,4,4,4,4,4,
 5,5,5,5,5,5,5,5,
 6,6,6,6,6,6,6,
 7,7,7,7,7,7,
 8,8,8,8,8,
 9,9,9,9,
 10,10,10,
 11,11,
 12};
__constant__ unsigned char PM[91] = {
 0,1,2,3,4,5,6,7,8,9,10,11,12,
 1,2,3,4,5,6,7,8,9,10,11,12,
 2,3,4,5,6,7,8,9,10,11,12,
 3,4,5,6,7,8,9,10,11,12,
 4,5,6,7,8,9,10,11,12,
 5,6,7,8,9,10,11,12,
 6,7,8,9,10,11,12,
 7,8,9,10,11,12,
 8,9,10,11,12,
 9,10,11,12,
 10,11,12,
 11,12,
 12};

__device__ __forceinline__ void ldrow16(const float* __restrict__ p, float* r) {
    float4 a = *reinterpret_cast<const float4*>(p);
    float4 b = *reinterpret_cast<const float4*>(p + 4);
    float4 c = *reinterpret_cast<const float4*>(p + 8);
    float4 d = *reinterpret_cast<const float4*>(p + 12);
    r[0]=a.x; r[1]=a.y; r[2]=a.z; r[3]=a.w;
    r[4]=b.x; r[5]=b.y; r[6]=b.z; r[7]=b.w;
    r[8]=c.x; r[9]=c.y; r[10]=c.z; r[11]=c.w;
    r[12]=d.x; r[13]=d.y; r[14]=d.z; r[15]=d.w;
}

__device__ __forceinline__ void ldrow13(const float* __restrict__ p, float* r) {
    float4 a = *reinterpret_cast<const float4*>(p);
    float4 b = *reinterpret_cast<const float4*>(p + 4);
    float4 c = *reinterpret_cast<const float4*>(p + 8);
    float last = p[12];
    r[0]=a.x; r[1]=a.y; r[2]=a.z; r[3]=a.w;
    r[4]=b.x; r[5]=b.y; r[6]=b.z; r[7]=b.w;
    r[8]=c.x; r[9]=c.y; r[10]=c.z; r[11]=c.w;
    r[12]=last;
}

__global__ void __launch_bounds__(TPB, 2) vae_kernel(
    const float* __restrict__ adj,
    const float* __restrict__ initW,
    const float* __restrict__ eps_param,
    const float* __restrict__ mlp_w0,
    const float* __restrict__ mlp_b0,
    const float* __restrict__ mlp_w1,
    const float* __restrict__ mlp_b1,
    const float* __restrict__ bn_in_gamma,
    const float* __restrict__ bn_in_beta,
    const float* __restrict__ bn_in_mean,
    const float* __restrict__ bn_in_var,
    const float* __restrict__ bn_out_gamma,
    const float* __restrict__ bn_out_beta,
    const float* __restrict__ bn_out_mean,
    const float* __restrict__ bn_out_var,
    const float* __restrict__ fc1_w,
    const float* __restrict__ fc1_b,
    const float* __restrict__ fc2_w,
    const float* __restrict__ fc2_b,
    const float* __restrict__ dec_w,
    const float* __restrict__ dec_b,
    float* __restrict__ out)
{
    extern __shared__ float sh[];
    const int tid = threadIdx.x;

    // ---------------- Phase A: cooperative loads ----------------
    {
        const float4* src = reinterpret_cast<const float4*>(adj + (size_t)blockIdx.x * NB * 676);
        for (int c = tid; c < NB * 169; c += TPB) {
            int bl = c / 169;
            int r  = c - bl * 169;
            float4 v = src[c];
            float vv[4] = {v.x, v.y, v.z, v.w};
            int e = 4 * r;
            #pragma unroll
            for (int j = 0; j < 4; ++j) {
                int ee = e + j;
                int ch = ee / 169;
                int p  = ee - ch * 169;
                int n  = p / 13;
                int m  = p - n * 13;
                sh[bl * RS + ch * 208 + n * 16 + m] = vv[j];
            }
        }
    }
    for (int j = tid; j < 208; j += TPB) sh[OW + j] = initW[j];
    for (int j = tid; j < 1024; j += TPB) {
        int l = j >> 8, r = j & 255, dp = r >> 4, c = r & 15;
        sh[OW0 + j] = mlp_w0[(l << 8) + (c << 4) + dp];
        sh[OW1 + j] = mlp_w1[(l << 8) + (c << 4) + dp];
        sh[ODEC + j] = dec_w[(l << 8) + (c << 4) + dp];   // [k][l][d] <- dec_w[k][d][l]
    }
    for (int j = tid; j < 64; j += TPB) {
        sh[OB0 + j] = mlp_b0[j];
        sh[OB1 + j] = mlp_b1[j];
        sh[ODECB + j] = dec_b[j];
    }
    for (int j = tid; j < 256; j += TPB) {
        int dp = j >> 4, c = j & 15;
        sh[OF1 + j] = fc1_w[(c << 4) + dp];
        sh[OF2 + j] = fc2_w[(c << 4) + dp];
    }
    for (int j = tid; j < 16; j += TPB) {
        sh[OF1B + j] = fc1_b[j];
        sh[OF2B + j] = fc2_b[j];
    }
    for (int j = tid; j < 52; j += TPB) {
        float s = bn_in_gamma[j] * rsqrtf(bn_in_var[j] + 1e-5f);
        sh[OBNI + 2*j]     = s;
        sh[OBNI + 2*j + 1] = bn_in_beta[j] - bn_in_mean[j] * s;
        float so = bn_out_gamma[j] * rsqrtf(bn_out_var[j] + 1e-5f);
        sh[OBNO + 2*j]     = so;
        sh[OBNO + 2*j + 1] = bn_out_beta[j] - bn_out_mean[j] * so;
    }
    for (int j = tid; j < 4; j += TPB) sh[OEPS + j] = 1.0f + eps_param[j];
    __syncthreads();

    // ---------------- Phase B: per-batch work (warp-local) ----------------
    const int lane = tid & 31;
    const int warp = tid >> 5;
    const int grp  = lane >> 3;       // batch within warp (0..3)
    const int t    = lane & 7;        // thread within batch, owns cols 2t, 2t+1
    const int bl   = warp * 4 + grp;
    const size_t b = (size_t)blockIdx.x * NB + bl;
    float* R  = sh + bl * RS;
    const int d0  = 2 * t;
    const int iCh = t >> 1;           // adj channel for owned col pair

    float* cur = R + X1OFF;           // x lives here at layer start
    float* alt = R + X0OFF;

    // S[n][*] = sum_ch adj[ch][n][*]  into alt(X0), padded rows
    for (int idx = t; idx < 52; idx += TB) {
        int n = idx >> 2, q = idx & 3;
        const float* p0 = R + n * 16 + q * 4;
        float4 a  = *reinterpret_cast<const float4*>(p0);
        float4 c1 = *reinterpret_cast<const float4*>(p0 + 208);
        float4 c2 = *reinterpret_cast<const float4*>(p0 + 416);
        float4 c3 = *reinterpret_cast<const float4*>(p0 + 624);
        float4 s;
        s.x = a.x + c1.x + c2.x + c3.x;
        s.y = a.y + c1.y + c2.y + c3.y;
        s.z = a.z + c1.z + c2.z + c3.z;
        s.w = a.w + c1.w + c2.w + c3.w;
        *reinterpret_cast<float4*>(alt + n * 16 + q * 4) = s;
    }
    __syncwarp();

    // init: x = S @ W   (alt -> cur)
    {
        float2 wi[NN];
        #pragma unroll
        for (int m = 0; m < NN; ++m)
            wi[m] = *reinterpret_cast<const float2*>(&sh[OW + m * 16 + d0]);
        #pragma unroll
        for (int n = 0; n < NN; ++n) {
            float rv[13]; ldrow13(alt + n * 16, rv);
            float a0 = 0.f, a1 = 0.f;
            #pragma unroll
            for (int m = 0; m < NN; ++m) {
                a0 = fmaf(rv[m], wi[m].x, a0);
                a1 = fmaf(rv[m], wi[m].y, a1);
            }
            *reinterpret_cast<float2*>(&cur[n * 16 + d0]) = make_float2(a0, a1);
        }
    }
    __syncwarp();

    // 4 GIN layers
    #pragma unroll 1
    for (int l = 0; l < 4; ++l) {
        const float ep = sh[OEPS + l];
        const float* A = R + iCh * 208;

        // agg: alt[n][d0:2] = ep*x[n] + (A @ x)[n]   (cur -> alt)
        {
            float2 xc[NN];
            #pragma unroll
            for (int m = 0; m < NN; ++m)
                xc[m] = *reinterpret_cast<const float2*>(&cur[m * 16 + d0]);
            #pragma unroll
            for (int n = 0; n < NN; ++n) {
                float rv[13]; ldrow13(A + n * 16, rv);
                float a0 = ep * xc[n].x, a1 = ep * xc[n].y;
                #pragma unroll
                for (int m = 0; m < NN; ++m) {
                    a0 = fmaf(rv[m], xc[m].x, a0);
                    a1 = fmaf(rv[m], xc[m].y, a1);
                }
                *reinterpret_cast<float2*>(&alt[n * 16 + d0]) = make_float2(a0, a1);
            }
        }
        __syncwarp();

        // MLP1 + bn_in + leaky: alt -> cur
        {
            float2 wv[DD];
            #pragma unroll
            for (int dp = 0; dp < DD; ++dp)
                wv[dp] = *reinterpret_cast<const float2*>(&sh[OW0 + (l << 8) + dp * 16 + d0]);
            float2 bb = *reinterpret_cast<const float2*>(&sh[OB0 + (l << 4) + d0]);
            float2 bn[NN];
            #pragma unroll
            for (int n = 0; n < NN; ++n)
                bn[n] = *reinterpret_cast<const float2*>(&sh[OBNI + l * 26 + n * 2]);
            #pragma unroll
            for (int n = 0; n < NN; ++n) {
                float rv[16]; ldrow16(alt + n * 16, rv);
                float a0 = bb.x, a1 = bb.y;
                #pragma unroll
                for (int dp = 0; dp < DD; ++dp) {
                    a0 = fmaf(rv[dp], wv[dp].x, a0);
                    a1 = fmaf(rv[dp], wv[dp].y, a1);
                }
                a0 = fmaf(a0, bn[n].x, bn[n].y);
                a1 = fmaf(a1, bn[n].x, bn[n].y);
                a0 = (a0 >= 0.f) ? a0 : 0.01f * a0;
                a1 = (a1 >= 0.f) ? a1 : 0.01f * a1;
                *reinterpret_cast<float2*>(&cur[n * 16 + d0]) = make_float2(a0, a1);
            }
        }
        __syncwarp();

        // MLP2 + bn_out + leaky: cur -> alt
        {
            float2 wv[DD];
            #pragma unroll
            for (int dp = 0; dp < DD; ++dp)
                wv[dp] = *reinterpret_cast<const float2*>(&sh[OW1 + (l << 8) + dp * 16 + d0]);
            float2 bb = *reinterpret_cast<const float2*>(&sh[OB1 + (l << 4) + d0]);
            float2 bn[NN];
            #pragma unroll
            for (int n = 0; n < NN; ++n)
                bn[n] = *reinterpret_cast<const float2*>(&sh[OBNO + l * 26 + n * 2]);
            #pragma unroll
            for (int n = 0; n < NN; ++n) {
                float rv[16]; ldrow16(cur + n * 16, rv);
                float a0 = bb.x, a1 = bb.y;
                #pragma unroll
                for (int dp = 0; dp < DD; ++dp) {
                    a0 = fmaf(rv[dp], wv[dp].x, a0);
                    a1 = fmaf(rv[dp], wv[dp].y, a1);
                }
                a0 = fmaf(a0, bn[n].x, bn[n].y);
                a1 = fmaf(a1, bn[n].x, bn[n].y);
                a0 = (a0 >= 0.f) ? a0 : 0.01f * a0;
                a1 = (a1 >= 0.f) ? a1 : 0.01f * a1;
                *reinterpret_cast<float2*>(&alt[n * 16 + d0]) = make_float2(a0, a1);
            }
        }
        __syncwarp();

        // new x is in alt
        float* tmp = cur; cur = alt; alt = tmp;
    }

    // fc1 -> mu (alt + gmem), fc2 -> logvar (gmem). x is in cur.
    {
        float2 wv[DD];
        #pragma unroll
        for (int dp = 0; dp < DD; ++dp)
            wv[dp] = *reinterpret_cast<const float2*>(&sh[OF1 + dp * 16 + d0]);
        float2 fb = *reinterpret_cast<const float2*>(&sh[OF1B + d0]);
        float* muG = out + MU_OFF + b * 208;
        #pragma unroll
        for (int n = 0; n < NN; ++n) {
            float rv[16]; ldrow16(cur + n * 16, rv);
            float a0 = fb.x, a1 = fb.y;
            #pragma unroll
            for (int dp = 0; dp < DD; ++dp) {
                a0 = fmaf(rv[dp], wv[dp].x, a0);
                a1 = fmaf(rv[dp], wv[dp].y, a1);
            }
            *reinterpret_cast<float2*>(&muG[n * 16 + d0]) = make_float2(a0, a1);
            *reinterpret_cast<float2*>(&alt[n * 16 + d0]) = make_float2(a0, a1);
        }
    }
    {
        float2 wv[DD];
        #pragma unroll
        for (int dp = 0; dp < DD; ++dp)
            wv[dp] = *reinterpret_cast<const float2*>(&sh[OF2 + dp * 16 + d0]);
        float2 fb = *reinterpret_cast<const float2*>(&sh[OF2B + d0]);
        float* lvG = out + LV_OFF + b * 208;
        #pragma unroll
        for (int n = 0; n < NN; ++n) {
            float rv[16]; ldrow16(cur + n * 16, rv);
            float a0 = fb.x, a1 = fb.y;
            #pragma unroll
            for (int dp = 0; dp < DD; ++dp) {
                a0 = fmaf(rv[dp], wv[dp].x, a0);
                a1 = fmaf(rv[dp], wv[dp].y, a1);
            }
            *reinterpret_cast<float2*>(&lvG[n * 16 + d0]) = make_float2(a0, a1);
        }
    }
    __syncwarp();   // mu (alt) visible to whole group

    // Decoder in two k-chunks; temp at R[0..416), recon scratch at R[416..754)
    float* outR = out + b * RECON_ELEMS;
    float* Rc = R + 416;
    #pragma unroll 1
    for (int c = 0; c < 2; ++c) {
        #pragma unroll
        for (int kk = 0; kk < 2; ++kk) {
            int k = 2 * c + kk;
            float2 wv[DD];
            #pragma unroll
            for (int li = 0; li < DD; ++li)
                wv[li] = *reinterpret_cast<const float2*>(&sh[ODEC + (k << 8) + li * 16 + d0]);
            float2 db = *reinterpret_cast<const float2*>(&sh[ODECB + (k << 4) + d0]);
            #pragma unroll
            for (int n = 0; n < NN; ++n) {
                float rv[16]; ldrow16(alt + n * 16, rv);
                float a0 = db.x, a1 = db.y;
                #pragma unroll
                for (int li = 0; li < DD; ++li) {
                    a0 = fmaf(rv[li], wv[li].x, a0);
                    a1 = fmaf(rv[li], wv[li].y, a1);
                }
                *reinterpret_cast<float2*>(&R[kk * 208 + n * 16 + d0]) = make_float2(a0, a1);
            }
        }
        __syncwarp();
        // recon = relu(temp @ temp^T), symmetric half
        for (int idx = t; idx < 182; idx += TB) {
            int kk = (idx >= 91) ? 1 : 0;
            int p = idx - kk * 91;
            int n = PN[p], m = PM[p];
            const float4* tn = reinterpret_cast<const float4*>(&R[kk * 208 + n * 16]);
            const float4* tm = reinterpret_cast<const float4*>(&R[kk * 208 + m * 16]);
            float s = 0.f;
            #pragma unroll
            for (int q = 0; q < 4; ++q) {
                float4 a = tn[q], bq = tm[q];
                s += a.x * bq.x + a.y * bq.y + a.z * bq.z + a.w * bq.w;
            }
            s = fmaxf(s, 0.f);
            Rc[kk * 169 + n * 13 + m] = s;
            Rc[kk * 169 + m * 13 + n] = s;
        }
        __syncwarp();
        // coalesced write: 338 floats = 169 float2
        {
            const float2* src2 = reinterpret_cast<const float2*>(Rc);
            float2* dst2 = reinterpret_cast<float2*>(outR + c * 338);
            for (int j = t; j < 169; j += TB) dst2[j] = src2[j];
        }
        __syncwarp();
    }
}

extern "C" void kernel_launch(void* const* d_in, const int* in_sizes, int n_in,
                              void* d_out, int out_size) {
    (void)in_sizes; (void)n_in; (void)out_size;
    cudaFuncSetAttribute(vae_kernel, cudaFuncAttributeMaxDynamicSharedMemorySize, SMEM_BYTES);
    vae_kernel<<<32768 / NB, TPB, SMEM_BYTES>>>(
        (const float*)d_in[0],  (const float*)d_in[1],  (const float*)d_in[2],
        (const float*)d_in[3],  (const float*)d_in[4],  (const float*)d_in[5],
        (const float*)d_in[6],  (const float*)d_in[7],  (const float*)d_in[8],
        (const float*)d_in[9],  (const float*)d_in[10], (const float*)d_in[11],
        (const float*)d_in[12], (const float*)d_in[13], (const float*)d_in[14],
        (const float*)d_in[15], (const float*)d_in[16], (const float*)d_in[17],
        (const float*)d_in[18], (const float*)d_in[19], (const float*)d_in[20],
        (float*)d_out);
}